// round 1
// baseline (speedup 1.0000x reference)
#include <cuda_runtime.h>
#include <cstdint>

// DenseRoutingMaskLayer: per-row argmax over 8 routing logits selects a
// contiguous 512-float chunk of the 4096-wide input row.
//   inputs:          [B=16384, D=4096] f32   (d_in[0])
//   routing_inputs:  [B=16384, R=8]    f32   (d_in[1])
//   out:             [B=16384, W=512]  f32
//
// One warp per row: lanes 0-7 fetch routing logits, shuffle-reduce argmax
// (first-index tie-break to match jnp.argmax), then the warp streams the
// selected 2KB chunk with 4 independent float4 loads/stores per lane.

__global__ __launch_bounds__(256, 8)
void dense_routing_mask_kernel(const float* __restrict__ inputs,
                               const float* __restrict__ routing,
                               float* __restrict__ out,
                               int B) {
    const int warps_per_block = blockDim.x >> 5;
    const int row  = blockIdx.x * warps_per_block + (threadIdx.x >> 5);
    const int lane = threadIdx.x & 31;
    if (row >= B) return;

    // ---- argmax over 8 routing logits (first occurrence wins) ----
    float v = -__int_as_float(0x7f800000);  // -inf
    int   idx = 0;
    if (lane < 8) {
        v   = routing[(size_t)row * 8 + lane];
        idx = lane;
    }
    #pragma unroll
    for (int off = 4; off > 0; off >>= 1) {
        float v2 = __shfl_down_sync(0xffffffffu, v,   off);
        int   i2 = __shfl_down_sync(0xffffffffu, idx, off);
        // shfl_down always brings a HIGHER original index, so on exact tie we
        // keep the current (lower) index -> first-occurrence semantics.
        if (v2 > v) { v = v2; idx = i2; }
    }
    idx = __shfl_sync(0xffffffffu, idx, 0);

    // ---- copy the selected 512-float chunk (128 x float4) ----
    const float4* __restrict__ src =
        reinterpret_cast<const float4*>(inputs + (size_t)row * 4096 + (size_t)idx * 512);
    float4* __restrict__ dst =
        reinterpret_cast<float4*>(out + (size_t)row * 512);

    #pragma unroll
    for (int i = 0; i < 4; i++) {
        dst[lane + i * 32] = src[lane + i * 32];
    }
}

extern "C" void kernel_launch(void* const* d_in, const int* in_sizes, int n_in,
                              void* d_out, int out_size) {
    const float* inputs  = (const float*)d_in[0];
    const float* routing = (const float*)d_in[1];
    float* out = (float*)d_out;

    const int B = in_sizes[1] / 8;  // routing_inputs has B*8 elements
    const int threads = 256;        // 8 warps/block, 1 warp per row
    const int blocks  = (B + 7) / 8;

    dense_routing_mask_kernel<<<blocks, threads>>>(inputs, routing, out, B);
}